// round 4
// baseline (speedup 1.0000x reference)
#include <cuda_runtime.h>
#include <cstdint>

// N=65536, D=512, C=1000.
// cp.async (LDGSTS) double-buffered pipeline: MLP lives in smem stages, not
// registers (ptxas defeated register front-batching in R2/R3).
// 304 blocks x 256 threads (2 blocks/SM on 152 SMs), chunk = 8 rows (warp/row),
// 3 stages x (16KB x + 16KB w) = 96KB dynamic smem per block.
// Fused deterministic final reduction via last-block-done counter.

#define N_ROWS   65536
#define D_DIM    512
#define THREADS  256
#define WARPS    8
#define ROWS_PER_CHUNK 8
#define NCHUNKS  (N_ROWS / ROWS_PER_CHUNK)    // 8192
#define GRIDB    304
#define STAGES   3
// floats per stage: 8 rows * 512 (x) + 8 rows * 512 (w) = 8192
#define STAGE_FLOATS 8192
#define SMEM_BYTES (STAGES * STAGE_FLOATS * 4)   // 98304

__device__ float g_partial[GRIDB];
__device__ int   g_count;   // zero-init; last block resets each call

__device__ __forceinline__ void cp_async16(uint32_t dst, const float* src) {
    asm volatile("cp.async.cg.shared.global [%0], [%1], 16;\n"
                 :: "r"(dst), "l"(src));
}
__device__ __forceinline__ void cp_commit() {
    asm volatile("cp.async.commit_group;\n");
}
__device__ __forceinline__ void cp_wait1() {
    asm volatile("cp.async.wait_group 1;\n");
}

__global__ __launch_bounds__(THREADS) void center_loss_pipe(
    const float* __restrict__ x,
    const float* __restrict__ w,
    const int*   __restrict__ t,
    float* __restrict__ out)
{
    extern __shared__ float smem[];
    const uint32_t smem_u32 = (uint32_t)__cvta_generic_to_shared(smem);

    const int tid  = threadIdx.x;
    const int wid  = tid >> 5;
    const int lane = tid & 31;
    const int bid  = blockIdx.x;

    // ---- stage issue helper (inlined via lambda-like macro logic) ----
    auto issue_stage = [&](int chunk, int stage, int cls) {
        const float* xsrc = x + ((size_t)chunk * ROWS_PER_CHUNK + wid) * D_DIM;
        const float* wsrc = w + (size_t)cls * D_DIM;
        uint32_t xdst = smem_u32 + (uint32_t)(stage * STAGE_FLOATS + wid * D_DIM) * 4u;
        uint32_t wdst = xdst + (uint32_t)(ROWS_PER_CHUNK / 2) * D_DIM * 4u * 2u; // +4096 floats
        #pragma unroll
        for (int kk = 0; kk < 4; kk++) {
            int e = (lane + kk * 32) * 4;             // float index within row
            cp_async16(xdst + (uint32_t)e * 4u, xsrc + e);
            cp_async16(wdst + (uint32_t)e * 4u, wsrc + e);
        }
    };

    // ---- prologue: fill STAGES-1 stages ----
    #pragma unroll
    for (int k = 0; k < STAGES - 1; k++) {
        int c = bid + k * GRIDB;
        if (c < NCHUNKS) {
            int cls = __ldg(&t[c * ROWS_PER_CHUNK + wid]);
            issue_stage(c, k, cls);
        }
        cp_commit();
    }

    float runsum = 0.0f;

    for (int k = 0; ; k++) {
        int c = bid + k * GRIDB;
        if (c >= NCHUNKS) break;

        // prefetch class index for the stage we will issue after compute
        int c_next = bid + (k + STAGES - 1) * GRIDB;
        int cls_next = 0;
        if (c_next < NCHUNKS)
            cls_next = __ldg(&t[c_next * ROWS_PER_CHUNK + wid]);

        cp_wait1();            // oldest group (chunk c) complete
        __syncthreads();

        // ---- compute chunk c from stage k%STAGES ----
        {
            const int sbase = (k % STAGES) * STAGE_FLOATS;
            const float4* xsr = reinterpret_cast<const float4*>(smem + sbase + wid * D_DIM);
            const float4* wsr = reinterpret_cast<const float4*>(smem + sbase + 4096 + wid * D_DIM);
            float acc = 0.0f;
            #pragma unroll
            for (int kk = 0; kk < 4; kk++) {
                float4 a = xsr[lane + kk * 32];
                float4 b = wsr[lane + kk * 32];
                float d;
                d = a.x - b.x; acc = fmaf(d, d, acc);
                d = a.y - b.y; acc = fmaf(d, d, acc);
                d = a.z - b.z; acc = fmaf(d, d, acc);
                d = a.w - b.w; acc = fmaf(d, d, acc);
            }
            #pragma unroll
            for (int o = 16; o > 0; o >>= 1)
                acc += __shfl_xor_sync(0xFFFFFFFFu, acc, o);
            runsum += sqrtf(acc + 1e-6f);   // same in all lanes; lane0 used later
        }
        __syncthreads();       // everyone done reading stage before overwrite

        if (c_next < NCHUNKS)
            issue_stage(c_next, (k + STAGES - 1) % STAGES, cls_next);
        cp_commit();
    }

    // ---- block reduction of per-warp sums ----
    __shared__ float sred[WARPS];
    if (lane == 0) sred[wid] = runsum;
    __syncthreads();

    __shared__ bool is_last;
    if (tid == 0) {
        float v = 0.0f;
        #pragma unroll
        for (int i = 0; i < WARPS; i++) v += sred[i];
        g_partial[bid] = v;
        __threadfence();
        int old = atomicAdd(&g_count, 1);
        is_last = (old == GRIDB - 1);
    }
    __syncthreads();

    if (is_last) {
        // deterministic reduce over GRIDB=304 partials with 256 threads
        float v = g_partial[tid];
        if (tid + THREADS < GRIDB) v += g_partial[tid + THREADS];
        #pragma unroll
        for (int o = 16; o > 0; o >>= 1)
            v += __shfl_xor_sync(0xFFFFFFFFu, v, o);
        __shared__ float fs[WARPS];
        if (lane == 0) fs[wid] = v;
        __syncthreads();
        if (tid < 32) {
            float u = (lane < WARPS) ? fs[lane] : 0.0f;
            #pragma unroll
            for (int o = 16; o > 0; o >>= 1)
                u += __shfl_xor_sync(0xFFFFFFFFu, u, o);
            if (tid == 0) {
                out[0] = u * (1.0f / (float)N_ROWS);
                g_count = 0;   // reset for next graph replay
            }
        }
    }
}

extern "C" void kernel_launch(void* const* d_in, const int* in_sizes, int n_in,
                              void* d_out, int out_size)
{
    const float* x = (const float*)d_in[0];   // [N, D] fp32
    const float* w = (const float*)d_in[1];   // [C, D] fp32
    const int*   t = (const int*)d_in[2];     // [N] int32
    float* out = (float*)d_out;

    cudaFuncSetAttribute(center_loss_pipe,
                         cudaFuncAttributeMaxDynamicSharedMemorySize, SMEM_BYTES);
    center_loss_pipe<<<GRIDB, THREADS, SMEM_BYTES>>>(x, w, t, out);
}

// round 5
// speedup vs baseline: 1.6256x; 1.6256x over previous
#include <cuda_runtime.h>
#include <cstdint>

// N=65536, D=512, C=1000.
// PER-WARP private cp.async pipeline: each warp owns 3 stages x 4KB
// (2KB x-row + 2KB gathered w-row) of smem and its own commit/wait ring.
// NO barriers in the main loop (R4's block-synchronous pipeline coupled all
// warps and failed). cp.async has no destination register, so ptxas cannot
// collapse the MLP (which killed R2/R3's register front-batching).
// Grid 304 x 256 (2 blocks/SM), fused deterministic final reduction.

#define N_ROWS   65536
#define D_DIM    512
#define BLOCKS   304
#define THREADS  256
#define WARPS    8
#define TOTAL_WARPS (BLOCKS * WARPS)    // 2432
#define STAGES   3
#define STAGE_FLOATS 1024               // 512 x + 512 w
#define WARP_SMEM_FLOATS (STAGES * STAGE_FLOATS)  // 3072
#define SMEM_BYTES (WARPS * WARP_SMEM_FLOATS * 4) // 98304

__device__ float g_partial[BLOCKS];
__device__ int   g_count;   // zero-init; last block resets each call

__device__ __forceinline__ void cp_async16(uint32_t dst, const float* src) {
    asm volatile("cp.async.cg.shared.global [%0], [%1], 16;\n" :: "r"(dst), "l"(src));
}
__device__ __forceinline__ void cp_commit() {
    asm volatile("cp.async.commit_group;\n");
}
__device__ __forceinline__ void cp_wait1() {
    asm volatile("cp.async.wait_group 1;\n");
}

__global__ __launch_bounds__(THREADS) void center_loss_pwp(
    const float* __restrict__ x,
    const float* __restrict__ w,
    const int*   __restrict__ t,
    float* __restrict__ out)
{
    extern __shared__ float smem[];
    const int tid  = threadIdx.x;
    const int wid  = tid >> 5;
    const int lane = tid & 31;
    const int gw   = blockIdx.x * WARPS + wid;   // global warp id

    const uint32_t warp_base =
        (uint32_t)__cvta_generic_to_shared(smem) + (uint32_t)(wid * WARP_SMEM_FLOATS) * 4u;

    // ---- per-warp stage issue: x row + gathered w row, 8 cp.async of 16B/lane
    auto issue = [&](int row, int cls, int s) {
        const float* xsrc = x + (size_t)row * D_DIM;
        const float* wsrc = w + (size_t)cls * D_DIM;
        uint32_t sb = warp_base + (uint32_t)(s * STAGE_FLOATS) * 4u;
        #pragma unroll
        for (int k = 0; k < 4; k++)
            cp_async16(sb + (uint32_t)(lane + k * 32) * 16u, xsrc + (lane + k * 32) * 4);
        #pragma unroll
        for (int k = 0; k < 4; k++)
            cp_async16(sb + 2048u + (uint32_t)(lane + k * 32) * 16u, wsrc + (lane + k * 32) * 4);
    };

    // ---- prologue: stages 0,1 ----
    #pragma unroll
    for (int k = 0; k < STAGES - 1; k++) {
        int row = gw + k * TOTAL_WARPS;
        if (row < N_ROWS) {
            int cls = __ldg(&t[row]);
            issue(row, cls, k);
        }
        cp_commit();
    }

    float runsum = 0.0f;

    for (int i = 0; ; i++) {
        int row = gw + i * TOTAL_WARPS;
        if (row >= N_ROWS) break;

        // prefetch class index for the row we'll issue after compute
        int nrow = gw + (i + 2) * TOTAL_WARPS;
        int ncls = 0;
        if (nrow < N_ROWS) ncls = __ldg(&t[nrow]);

        cp_wait1();   // oldest group (this row's stage) complete; per-warp state

        const int s = i % STAGES;
        const float4* xs = reinterpret_cast<const float4*>(
            smem + (size_t)wid * WARP_SMEM_FLOATS + s * STAGE_FLOATS);
        const float4* ws = xs + 128;   // +512 floats

        float acc = 0.0f;
        #pragma unroll
        for (int k = 0; k < 4; k++) {
            float4 a = xs[lane + k * 32];
            float4 b = ws[lane + k * 32];
            float d;
            d = a.x - b.x; acc = fmaf(d, d, acc);
            d = a.y - b.y; acc = fmaf(d, d, acc);
            d = a.z - b.z; acc = fmaf(d, d, acc);
            d = a.w - b.w; acc = fmaf(d, d, acc);
        }
        #pragma unroll
        for (int o = 16; o > 0; o >>= 1)
            acc += __shfl_xor_sync(0xFFFFFFFFu, acc, o);
        runsum += sqrtf(acc + 1e-6f);   // replicated across lanes

        // stage (i+2)%3 was consumed at iter i-1 by this same warp: safe to refill
        if (nrow < N_ROWS) issue(nrow, ncls, (i + 2) % STAGES);
        cp_commit();   // one group per iteration, possibly empty
    }

    // ---- block reduction of per-warp sums ----
    __shared__ float sred[WARPS];
    if (lane == 0) sred[wid] = runsum;
    __syncthreads();

    __shared__ bool is_last;
    if (tid == 0) {
        float v = 0.0f;
        #pragma unroll
        for (int i = 0; i < WARPS; i++) v += sred[i];
        g_partial[blockIdx.x] = v;
        __threadfence();
        int old = atomicAdd(&g_count, 1);
        is_last = (old == BLOCKS - 1);
    }
    __syncthreads();

    if (is_last) {
        float v = (tid < BLOCKS) ? g_partial[tid] : 0.0f;
        if (tid + THREADS < BLOCKS) v += g_partial[tid + THREADS];
        #pragma unroll
        for (int o = 16; o > 0; o >>= 1)
            v += __shfl_xor_sync(0xFFFFFFFFu, v, o);
        __shared__ float fs[WARPS];
        if (lane == 0) fs[wid] = v;
        __syncthreads();
        if (tid < 32) {
            float u = (lane < WARPS) ? fs[lane] : 0.0f;
            #pragma unroll
            for (int o = 16; o > 0; o >>= 1)
                u += __shfl_xor_sync(0xFFFFFFFFu, u, o);
            if (tid == 0) {
                out[0] = u * (1.0f / (float)N_ROWS);
                g_count = 0;   // reset for next graph replay
            }
        }
    }
}

extern "C" void kernel_launch(void* const* d_in, const int* in_sizes, int n_in,
                              void* d_out, int out_size)
{
    const float* x = (const float*)d_in[0];   // [N, D] fp32
    const float* w = (const float*)d_in[1];   // [C, D] fp32
    const int*   t = (const int*)d_in[2];     // [N] int32
    float* out = (float*)d_out;

    cudaFuncSetAttribute(center_loss_pwp,
                         cudaFuncAttributeMaxDynamicSharedMemorySize, SMEM_BYTES);
    center_loss_pwp<<<BLOCKS, THREADS, SMEM_BYTES>>>(x, w, t, out);
}